// round 17
// baseline (speedup 1.0000x reference)
#include <cuda_runtime.h>

#define NBLK 128
#define TPB  512
#define TILE 128
#define NRED 34          // reducer blocks; 34*8 = 272 float4 elements
#define EPSV 1e-10f

__device__ __align__(16) float4 g_partial4T[272][NBLK];  // [element][block]
__device__ __align__(16) float2 g_gramF[1024];           // full mirrored 32x32 Gram
__device__ unsigned g_arrive;    // monotonic; +128 per launch
__device__ unsigned g_reddone;   // monotonic; +34  per launch

__device__ __forceinline__ unsigned long long pk2(float lo, float hi) {
    unsigned long long r;
    asm("mov.b64 %0, {%1, %2};" : "=l"(r) : "f"(lo), "f"(hi));
    return r;
}
__device__ __forceinline__ unsigned long long fma2(unsigned long long a,
                                                   unsigned long long b,
                                                   unsigned long long c) {
    unsigned long long d;
    asm("fma.rn.f32x2 %0, %1, %2, %3;" : "=l"(d) : "l"(a), "l"(b), "l"(c));
    return d;
}
__device__ __forceinline__ float2 upk2(unsigned long long v) {
    float lo, hi;
    asm("mov.b64 {%0, %1}, %2;" : "=f"(lo), "=f"(hi) : "l"(v));
    return make_float2(lo, hi);
}

__global__ __launch_bounds__(TPB, 1) void k_all(const float2* __restrict__ x,
                                                float2* __restrict__ y) {
    __shared__ __align__(16) char smem[49152];   // [0,32K) xs | [32K,48K) AUX
    int tid = threadIdx.x;
    int blk = blockIdx.x;

    float2 (*xs)[32] = (float2(*)[32])smem;      // 128 x 32 float2, resident
    char* AUX = smem + 32768;                    // 16KB: pbuf / Rs+Ss / P planes

    // ================= phase 1: stage x tile, Hermitian partial Gram ========
    const float4* src = (const float4*)(x + (size_t)blk * TILE * 32);
    {
        float4* dst = (float4*)smem;
#pragma unroll
        for (int t = 0; t < 4; t++) dst[tid + TPB * t] = src[tid + TPB * t];
    }
    __syncthreads();

    {
        // flat jobs 0..271: job = tile + 136*mgroup -> active warps 0..8
        bool active = (tid < 272);
        int tile = (tid < 136) ? tid : tid - 136;
        int mg   = (tid < 136) ? 0 : 1;
        int i0 = 0, j0 = 0;
        if (active) {
            int tt = tile, ti = 0;
            while (tt >= 16 - ti) { tt -= 16 - ti; ti++; }
            i0 = ti * 2;
            j0 = (ti + tt) * 2;
        }
        float a00x = 0.f, a00y = 0.f, a01x = 0.f, a01y = 0.f;
        float a10x = 0.f, a10y = 0.f, a11x = 0.f, a11y = 0.f;
        if (active) {
            int mbase = mg * 64;
#pragma unroll 8
            for (int mm = 0; mm < 64; mm++) {
                float4 av = *(const float4*)&xs[mbase + mm][i0];
                float4 bv = *(const float4*)&xs[mbase + mm][j0];
                a00x += av.x * bv.x + av.y * bv.y;  a00y += av.x * bv.y - av.y * bv.x;
                a01x += av.x * bv.z + av.y * bv.w;  a01y += av.x * bv.w - av.y * bv.z;
                a10x += av.z * bv.x + av.w * bv.y;  a10y += av.z * bv.y - av.w * bv.x;
                a11x += av.z * bv.z + av.w * bv.w;  a11y += av.z * bv.w - av.w * bv.z;
            }
        }
        float2* P = (float2*)AUX;    // 4 x 136 float2 combine buffer
        if (active && mg == 1) {
            P[0 * 136 + tile] = make_float2(a00x, a00y);
            P[1 * 136 + tile] = make_float2(a01x, a01y);
            P[2 * 136 + tile] = make_float2(a10x, a10y);
            P[3 * 136 + tile] = make_float2(a11x, a11y);
        }
        __syncthreads();
        if (active && mg == 0) {
            float2 q;
            q = P[0 * 136 + tile]; a00x += q.x; a00y += q.y;
            q = P[1 * 136 + tile]; a01x += q.x; a01y += q.y;
            q = P[2 * 136 + tile]; a10x += q.x; a10y += q.y;
            q = P[3 * 136 + tile]; a11x += q.x; a11y += q.y;
            // transposed layout: scattered stores (fire-and-forget), coalesced reads
            g_partial4T[tile * 2][blk]     = make_float4(a00x, a00y, a01x, a01y);
            g_partial4T[tile * 2 + 1][blk] = make_float4(a10x, a10y, a11x, a11y);
        }
    }

    __threadfence();          // release partial stores
    __syncthreads();
    unsigned rep = 0;
    if (tid == 0) {
        unsigned v = atomicAdd(&g_arrive, 1u);
        rep = (v >> 7) + 1u;  // launch index; arrive target = rep*128
    }

    // ======= distributed reduce: 34 blocks, warp-per-element, mirrored ======
    if (blk < NRED) {
        if (tid == 0) {
            unsigned target = rep << 7;
            while ((int)(*(volatile unsigned*)&g_arrive - target) < 0) { }
            __threadfence();  // acquire partials
        }
        __syncthreads();
        int w = tid >> 5, l = tid & 31;
        if (w < 8) {
            int e = blk * 8 + w;                    // 0..271
            // coalesced: lanes read contiguous float4 along the block axis
            float4 p  = g_partial4T[e][l];
            float4 q1 = g_partial4T[e][l + 32];
            float4 q2 = g_partial4T[e][l + 64];
            float4 q3 = g_partial4T[e][l + 96];
            p.x = ((p.x + q1.x) + q2.x) + q3.x;
            p.y = ((p.y + q1.y) + q2.y) + q3.y;
            p.z = ((p.z + q1.z) + q2.z) + q3.z;
            p.w = ((p.w + q1.w) + q2.w) + q3.w;
#pragma unroll
            for (int off = 16; off > 0; off >>= 1) {
                p.x += __shfl_xor_sync(0xffffffffu, p.x, off);
                p.y += __shfl_xor_sync(0xffffffffu, p.y, off);
                p.z += __shfl_xor_sync(0xffffffffu, p.z, off);
                p.w += __shfl_xor_sync(0xffffffffu, p.w, off);
            }
            if (l == 0) {
                // e = tile L, row half h; write direct + Hermitian mirror
                int L = e >> 1, h = e & 1;
                int tt = L, ti = 0;
                while (tt >= 16 - ti) { tt -= 16 - ti; ti++; }
                int tj = ti + tt;
                int i  = 2 * ti + h;
                int j0 = 2 * tj;
                g_gramF[i * 32 + j0]       = make_float2(p.x, p.y);
                g_gramF[i * 32 + j0 + 1]   = make_float2(p.z, p.w);
                g_gramF[j0 * 32 + i]       = make_float2(p.x, -p.y);
                g_gramF[(j0 + 1) * 32 + i] = make_float2(p.z, -p.w);
            }
        }
        __threadfence();
        __syncthreads();
        if (tid == 0) atomicAdd(&g_reddone, 1u);
    }

    // ================= every block: wait for Gram, solve locally ============
    if (tid == 0) {
        unsigned target = rep * NRED;
        while ((int)(*(volatile unsigned*)&g_reddone - target) < 0) { }
        __threadfence();  // acquire g_gramF
    }
    __syncthreads();

    float2 (*Rs)[32] = (float2(*)[32])AUX;             // 8KB
    float2 (*Ss)[32] = (float2(*)[32])(AUX + 8192);    // 8KB; Tmp lives in
                                                       // Ss rows 16-31 cols 0-15
    // ---- register+shfl Cholesky (upper), warp 0, lane = column k ----------
    if (tid < 32) {
        int k = tid;
        float2 a[32];
#pragma unroll
        for (int i = 0; i < 32; i++) a[i] = g_gramF[i * 32 + k];   // coalesced
#pragma unroll
        for (int j = 0; j < 32; j++) {
            float d = __shfl_sync(0xffffffffu, a[j].x, j) + EPSV;
            float inv = rsqrtf(d);
            float rjj = d * inv;                       // sqrt(d)
            float rx, ry;
            if (k > j)       { rx = a[j].x * inv; ry = a[j].y * inv; }
            else if (k == j) { rx = rjj; ry = 0.f; }
            else             { rx = 0.f; ry = 0.f; }
            // diag slot stashes inv in .y (never read as a matrix entry)
            Rs[j][k] = (k == j) ? make_float2(rjj, inv) : make_float2(rx, ry);
            // a[i] -= conj(R[j][i]) * R[j][k]  for i > j
#pragma unroll
            for (int i = j + 1; i < 32; i++) {
                float bx = __shfl_sync(0xffffffffu, rx, i);
                float by = __shfl_sync(0xffffffffu, ry, i);
                a[i].x -= bx * rx + by * ry;
                a[i].y -= bx * ry - by * rx;
            }
        }
    }
    __syncthreads();

    // ---- register back-substitution: S11 (lanes 0-15), S22 (16-31) --------
    if (tid < 32) {
        int half = tid >> 4;
        int j = tid & 15;
        int base = half * 16;
        float2 s[16];
#pragma unroll
        for (int i = 15; i >= 0; i--) {
            if (i == j) {
                s[i] = make_float2(Rs[base + i][base + i].y, 0.f);   // invd
            } else if (i < j) {
                float ax = 0.f, ay = 0.f;
#pragma unroll
                for (int k = i + 1; k < 16; k++) {
                    float2 sv = (k <= j) ? s[k] : make_float2(0.f, 0.f);
                    float2 rv = Rs[base + i][base + k];
                    ax += rv.x * sv.x - rv.y * sv.y;
                    ay += rv.x * sv.y + rv.y * sv.x;
                }
                float inv = Rs[base + i][base + i].y;
                s[i] = make_float2(-ax * inv, -ay * inv);
            }
        }
#pragma unroll
        for (int i = 0; i < 16; i++)
            if (i <= j) Ss[base + i][base + j] = s[i];
    }
    __syncthreads();

    // Tmp = R12 * S22  (Tmp(i,j) -> Ss[16+i][j], unused lower-left quadrant)
    if (tid < 256) {
        int i = tid >> 4, j = tid & 15;
        float ax = 0.f, ay = 0.f;
#pragma unroll
        for (int k = 0; k < 16; k++) {
            if (k <= j) {                      // S22 upper-triangular
                float2 rv = Rs[i][16 + k];
                float2 sv = Ss[16 + k][16 + j];
                ax += rv.x * sv.x - rv.y * sv.y;
                ay += rv.x * sv.y + rv.y * sv.x;
            }
        }
        Ss[16 + i][j] = make_float2(ax, ay);
    }
    __syncthreads();
    // S12 = -S11 * Tmp
    if (tid < 256) {
        int i = tid >> 4, j = tid & 15;
        float ax = 0.f, ay = 0.f;
#pragma unroll
        for (int k = 0; k < 16; k++) {
            if (k >= i) {                      // S11 upper-triangular
                float2 sv = Ss[i][k];
                float2 tv = Ss[16 + k][j];     // Tmp
                ax += sv.x * tv.x - sv.y * tv.y;
                ay += sv.x * tv.y + sv.y * tv.x;
            }
        }
        Ss[i][16 + j] = make_float2(-ax, -ay);
    }
    __syncthreads();

    // ================= phase 3: pack T planes, apply Y = X * T ==============
    {
        unsigned long long (*P1)[32] = (unsigned long long(*)[32])AUX;           // (tr0,tr1)
        unsigned long long (*P2)[32] = (unsigned long long(*)[32])(AUX + 4096);  // (ti0,ti1)
        unsigned long long (*P3)[32] = (unsigned long long(*)[32])(AUX + 8192);  // (-ti0,-ti1)
        {
            int k2 = tid >> 5, jj = tid & 31;   // 16 k-pairs x 32 cols
            int rlo = 2 * k2, rhi = 2 * k2 + 1;
            float2 v0 = (rlo <= jj) ? Ss[rlo][jj] : make_float2(0.f, 0.f);
            float2 v1 = (rhi <= jj) ? Ss[rhi][jj] : make_float2(0.f, 0.f);
            __syncthreads();                    // all T reads done before overlay
            P1[k2][jj] = pk2(v0.x, v1.x);
            P2[k2][jj] = pk2(v0.y, v1.y);
            P3[k2][jj] = pk2(-v0.y, -v1.y);
        }
        __syncthreads();

        int j  = tid & 31;
        int r0 = (tid >> 5) * 8;   // 16 warps x 8 rows = 128 rows

        unsigned long long accx[8], accy[8];
        unsigned long long z = pk2(0.f, 0.f);
#pragma unroll
        for (int r = 0; r < 8; r++) { accx[r] = z; accy[r] = z; }

#pragma unroll
        for (int k2 = 0; k2 < 16; k2++) {
            unsigned long long p1 = P1[k2][j];
            unsigned long long p2 = P2[k2][j];
            unsigned long long p3 = P3[k2][j];
#pragma unroll
            for (int r = 0; r < 8; r++) {
                float4 a = *(const float4*)&xs[r0 + r][2 * k2];  // (re0,im0,re1,im1)
                unsigned long long arr = pk2(a.x, a.z);
                unsigned long long aii = pk2(a.y, a.w);
                accx[r] = fma2(arr, p1, accx[r]);
                accx[r] = fma2(aii, p3, accx[r]);
                accy[r] = fma2(arr, p2, accy[r]);
                accy[r] = fma2(aii, p1, accy[r]);
            }
        }

        size_t base = (size_t)blk * TILE + r0;
#pragma unroll
        for (int r = 0; r < 8; r++) {
            float2 fx = upk2(accx[r]);
            float2 fy = upk2(accy[r]);
            y[(base + r) * 32 + j] = make_float2(fx.x + fx.y, fy.x + fy.y);
        }
    }
}

// ---------------------------------------------------------------------------
extern "C" void kernel_launch(void* const* d_in, const int* in_sizes, int n_in,
                              void* d_out, int out_size) {
    const float2* x = (const float2*)d_in[0];
    float2* y = (float2*)d_out;
    (void)in_sizes; (void)n_in; (void)out_size;

    k_all<<<NBLK, TPB>>>(x, y);
}